// round 9
// baseline (speedup 1.0000x reference)
#include <cuda_runtime.h>

#define BB 32
#define NN 16384
#define PP 4096
#define CC 14
#define TPB 256
#define PTS 4
#define SEGS (NN / (TPB * PTS))          // 16 dist segments per batch
#define NBLK (BB * SEGS)                 // 512 blocks (all co-resident at 4/SM)
#define CBB 8                            // segs 0..7 do centroid binning (2 pts/thread)
#define NW (TPB / 32)                    // 8 warps

// all zero-initialized at module load; every replay restores them
__device__ unsigned g_count;
__device__ unsigned g_bcnt[BB];
__device__ float    g_sums[BB][CC * 4];  // float4-aligned per class
__device__ float4   g_centP[BB][CC];     // (-2cx, -2cy, -2cz, ||c||^2)
__device__ unsigned g_flag[BB];
__device__ float    g_part[NBLK];

__device__ __forceinline__ float smooth_l1(float x) {
    const float ax = fabsf(x);
    return (ax < 1.0f) ? (0.5f * x * x) : (ax - 0.5f);
}
__device__ __forceinline__ float sqrt_fast(float x) {
    float r; asm("sqrt.approx.f32 %0, %1;" : "=f"(r) : "f"(x)); return r;
}
__device__ __forceinline__ unsigned ld_acq(const unsigned* p) {
    unsigned v;
    asm volatile("ld.acquire.gpu.u32 %0, [%1];" : "=r"(v) : "l"(p) : "memory");
    return v;
}
__device__ __forceinline__ void st_rel(unsigned* p, unsigned v) {
    asm volatile("st.release.gpu.u32 [%0], %1;" :: "l"(p), "r"(v) : "memory");
}
__device__ __forceinline__ unsigned atom_inc_acqrel(unsigned* p) {
    unsigned old;
    asm volatile("atom.acq_rel.gpu.add.u32 %0, [%1], %2;"
                 : "=r"(old) : "l"(p), "r"(1u) : "memory");
    return old;
}

__global__ void __launch_bounds__(TPB, 4) k_fused(
        const float* __restrict__ disp, const float* __restrict__ sub,
        const float* __restrict__ cpred, const float* __restrict__ origin,
        const int* __restrict__ tgt, float* __restrict__ out)
{
    const int bid = blockIdx.x;
    const int tid = threadIdx.x;
    const int lane = tid & 31, wid = tid >> 5;
    const int b = bid / SEGS;
    const int seg = bid % SEGS;

    __shared__ float red[NW][64];
    __shared__ float s_cgx[CC], s_cgy[CC], s_cgz[CC];
    __shared__ float4 s_c[CC];
    __shared__ float wsum[NW];
    __shared__ double dsum[NW];
    __shared__ int s_lastc, s_win;

    float extra = 0.0f;   // chamfer+separation (winner-block tid0 only)

    // ================= phase 1: centroids (segs 0..7, 2 pts/thread) =================
    if (seg < CBB) {
        const int base = seg * (PP / CBB);            // 512 points per block
        const float* __restrict__ ox = origin + (size_t)b * 9 * PP + base;
        const float* __restrict__ oy = ox + PP;
        const float* __restrict__ oz = ox + 2 * PP;
        const int* __restrict__ tg = tgt + (size_t)b * PP + base;

        const int2 c2   = *(const int2*)(tg + tid * 2);
        const float2 x2 = *(const float2*)(ox + tid * 2);
        const float2 y2 = *(const float2*)(oy + tid * 2);
        const float2 z2 = *(const float2*)(oz + tid * 2);
        const int cs[2] = {c2.x, c2.y};
        const float px[2] = {x2.x, x2.y};
        const float py[2] = {y2.x, y2.y};
        const float pz[2] = {z2.x, z2.y};

        // padded bins: [class*4 + comp], 56..63 stay zero
        float v[64];
        #pragma unroll
        for (int k = 0; k < 64; k++) v[k] = 0.0f;
        #pragma unroll
        for (int i = 0; i < 2; i++) {
            const int c = cs[i];
            #pragma unroll
            for (int cc = 0; cc < CC; cc++) {
                if (c == cc) {             // predicated FADDs
                    v[cc * 4 + 0] += px[i];
                    v[cc * 4 + 1] += py[i];
                    v[cc * 4 + 2] += pz[i];
                    v[cc * 4 + 3] += 1.0f;
                }
            }
        }

        // reduce-scatter: 5 exchange levels; lane l ends owning totals 2l, 2l+1
        #pragma unroll
        for (int off = 16, cnt = 64; off >= 1; off >>= 1, cnt >>= 1) {
            const int half = cnt >> 1;
            const bool hi = (lane & off) != 0;
            #pragma unroll
            for (int i = 0; i < 32; i++) {
                if (i < half) {
                    const float send = hi ? v[i] : v[i + half];
                    const float recv = __shfl_xor_sync(0xFFFFFFFFu, send, off);
                    const float keep = hi ? v[i + half] : v[i];
                    v[i] = keep + recv;
                }
            }
        }
        if (lane < 28) {
            red[wid][2 * lane]     = v[0];
            red[wid][2 * lane + 1] = v[1];
        }
        __syncthreads();
        if (tid < CC * 4) {
            float s = 0.0f;
            #pragma unroll
            for (int w = 0; w < NW; w++) s += red[w][tid];
            atomicAdd(&g_sums[b][tid], s);   // relaxed; published by acq_rel below
        }
        __syncthreads();
        if (tid == 0)
            s_lastc = (atom_inc_acqrel(&g_bcnt[b]) == CBB - 1);
        __syncthreads();

        if (s_lastc) {
            if (tid < CC) {
                const float4 f = *(const float4*)&g_sums[b][tid * 4];
                *(float4*)&g_sums[b][tid * 4] = make_float4(0.f, 0.f, 0.f, 0.f);  // reset
                const float inv = 1.0f / fmaxf(f.w, 1.0f);
                const float x = f.x * inv, y = f.y * inv, z = f.z * inv;
                s_cgx[tid] = x; s_cgy[tid] = y; s_cgz[tid] = z;
                g_centP[b][tid] = make_float4(-2.0f * x, -2.0f * y, -2.0f * z,
                                              fmaf(x, x, fmaf(y, y, z * z)));
            }
            __syncthreads();
            if (tid == 0) {
                g_bcnt[b] = 0;
                st_rel(&g_flag[b], 1u);      // release dist blocks ASAP
            }
            // chamfer + separation overlaps pollers' dist start
            if (tid < 32) {
                float local = 0.0f;
                if (tid < CC) {
                    const float* __restrict__ cp = cpred + (size_t)b * 3 * CC;
                    const float qx = cp[tid], qy = cp[CC + tid], qz = cp[2 * CC + tid];
                    float rmin = 3.4e38f, m1 = 3.4e38f, m2 = 3.4e38f;
                    #pragma unroll
                    for (int j = 0; j < CC; j++) {
                        const float dx = qx - s_cgx[j], dy = qy - s_cgy[j], dz = qz - s_cgz[j];
                        const float d2 = fmaf(dx, dx, fmaf(dy, dy, dz * dz));
                        rmin = fminf(rmin, d2);
                        const float dd = sqrt_fast(d2);
                        if (dd < m1) { m2 = m1; m1 = dd; }
                        else if (dd < m2) { m2 = dd; }
                    }
                    const float gx = s_cgx[tid], gy = s_cgy[tid], gz = s_cgz[tid];
                    float cmin = 3.4e38f;
                    #pragma unroll
                    for (int i = 0; i < CC; i++) {
                        const float dx = cp[i] - gx, dy = cp[CC + i] - gy, dz = cp[2 * CC + i] - gz;
                        cmin = fminf(cmin, fmaf(dx, dx, fmaf(dy, dy, dz * dz)));
                    }
                    local = rmin + cmin + 0.1f * (m1 / m2);
                }
                #pragma unroll
                for (int off = 16; off > 0; off >>= 1)
                    local += __shfl_xor_sync(0xFFFFFFFFu, local, off);
                if (tid == 0) extra = local;
            }
        }
    }

    // ================= phase 2: distance loss (all 512 blocks, 4 pts/thread) ========
    {
        const float* __restrict__ dp = disp + (size_t)b * NN;
        const float* __restrict__ sx = sub + (size_t)b * 3 * NN;
        const float* __restrict__ sy = sx + NN;
        const float* __restrict__ sz = sx + 2 * NN;
        const int o0 = seg * (TPB * PTS) + tid * 4;

        // issue all loads + ||p||^2 BEFORE the spin
        const float4 d4 = *(const float4*)(dp + o0);
        const float4 x4 = *(const float4*)(sx + o0);
        const float4 y4 = *(const float4*)(sy + o0);
        const float4 z4 = *(const float4*)(sz + o0);

        const float xs[4] = {x4.x, x4.y, x4.z, x4.w};
        const float ys[4] = {y4.x, y4.y, y4.z, y4.w};
        const float zs[4] = {z4.x, z4.y, z4.z, z4.w};
        const float ds[4] = {d4.x, d4.y, d4.z, d4.w};
        float pn[4];
        #pragma unroll
        for (int k = 0; k < 4; k++)
            pn[k] = fmaf(xs[k], xs[k], fmaf(ys[k], ys[k], zs[k] * zs[k]));

        // acquire-poll + fetch packed centroids (lanes 0..13 of warp 0)
        if (tid < CC) {
            while (ld_acq(&g_flag[b]) == 0u) __nanosleep(32);
            s_c[tid] = g_centP[b][tid];
        }
        __syncthreads();

        float tmin[4];
        #pragma unroll
        for (int k = 0; k < 4; k++) tmin[k] = 3.4e38f;
        #pragma unroll
        for (int c = 0; c < CC; c++) {
            const float4 cp = s_c[c];
            #pragma unroll
            for (int k = 0; k < 4; k++) {
                const float t = fmaf(xs[k], cp.x, fmaf(ys[k], cp.y, fmaf(zs[k], cp.z, cp.w)));
                tmin[k] = fminf(tmin[k], t);
            }
        }
        float local = 0.0f;
        #pragma unroll
        for (int k = 0; k < 4; k++) {
            const float d2 = fmaxf(pn[k] + tmin[k], 0.0f);
            local += smooth_l1(ds[k] - sqrt_fast(d2));
        }

        #pragma unroll
        for (int off = 16; off > 0; off >>= 1)
            local += __shfl_xor_sync(0xFFFFFFFFu, local, off);
        if (lane == 0) wsum[wid] = local;
        __syncthreads();

        if (tid == 0) {
            float v2 = extra;
            #pragma unroll
            for (int w = 0; w < NW; w++) v2 += wsum[w];
            g_part[bid] = v2;                                  // plain store
            s_win = (atom_inc_acqrel(&g_count) == NBLK - 1);   // release publishes it
        }
        __syncthreads();

        if (s_win) {
            // 512 partials, 2 per thread
            double dv = (double)g_part[tid] + (double)g_part[tid + TPB];
            #pragma unroll
            for (int off = 16; off > 0; off >>= 1)
                dv += __shfl_xor_sync(0xFFFFFFFFu, dv, off);
            if (lane == 0) dsum[wid] = dv;
            __syncthreads();
            if (tid == 0) {
                double tot = 0.0;
                #pragma unroll
                for (int w = 0; w < NW; w++) tot += dsum[w];
                out[0] = (float)tot;
                g_count = 0;
            }
            if (tid < BB) g_flag[tid] = 0;
        }
    }
}

extern "C" void kernel_launch(void* const* d_in, const int* in_sizes, int n_in,
                              void* d_out, int out_size) {
    const float* disp   = (const float*)d_in[0];       // [B, N]
    const float* sub    = (const float*)d_in[1];       // [B, 3, N]
    const float* cpred  = (const float*)d_in[2];       // [B, 3, C]
    const float* origin = (const float*)d_in[3];       // [B, 9, P]
    const int*   tg     = (const int*)d_in[4];         // [B, P]
    float* out = (float*)d_out;

    k_fused<<<NBLK, TPB>>>(disp, sub, cpred, origin, tg, out);
}